// round 5
// baseline (speedup 1.0000x reference)
#include <cuda_runtime.h>
#include <cuda_bf16.h>
#include <cstdint>

#define NTH 256
constexpr int TB   = 64;
constexpr int NH   = 100;
constexpr int NPAD = 112;
constexpr int KD   = 64;
constexpr int DIMS = 8;
constexpr int TOT  = 512;
constexpr int WKS  = 120;   // halves: stride for W2/W3/H buffers (conflict-free ldmatrix)
constexpr int W1KS = 72;    // halves: W1 slice stride
constexpr int ZBS  = 72;    // halves: z-buffer stride

// shared layout (word offsets)
constexpr int O_W2S = 0;                    // [112][60w]
constexpr int O_W2T = O_W2S + NPAD * 60;    // 6720
constexpr int O_W3S = O_W2T + NPAD * 60;    // 13440 [64][60w]
constexpr int O_W3T = O_W3S + 64 * 60;      // 17280
constexpr int O_W1S = O_W3T + 64 * 60;      // 21120 [112][36w]
constexpr int O_W1T = O_W1S + NPAD * 36;    // 25152
constexpr int O_H1S = O_W1T + NPAD * 36;    // 29184 [64][60w]
constexpr int O_H1T = O_H1S + TB * 60;      // 33024
constexpr int O_H2S = O_H1T + TB * 60;      // 36864
constexpr int O_H2T = O_H2S + TB * 60;      // 40704
constexpr int O_ZB  = O_H2T + TB * 60;      // 44544 [64][36w] bf16 z
constexpr int O_LDP = O_ZB + TB * 36;       // 46848 [64][8]
constexpr int O_B1S = O_LDP + TB * 8;       // 47360
constexpr int O_B2S = O_B1S + NPAD;
constexpr int O_B3S = O_B2S + NPAD;
constexpr int O_B1T = O_B3S + KD;
constexpr int O_B2T = O_B1T + NPAD;
constexpr int O_B3T = O_B2T + NPAD;
constexpr int SMW   = O_B3T + KD;           // 47936 words = 191744 B

__device__ __forceinline__ float sigm(float x) {
    return __fdividef(1.0f, 1.0f + __expf(-x));
}

__device__ __forceinline__ uint32_t sm_u32(const void* p) {
    uint32_t a;
    asm("{ .reg .u64 t; cvta.to.shared.u64 t, %1; cvt.u32.u64 %0, t; }" : "=r"(a) : "l"(p));
    return a;
}

__device__ __forceinline__ void ldsm4(uint32_t a, uint32_t r[4]) {
    asm volatile("ldmatrix.sync.aligned.m8n8.x4.shared.b16 {%0,%1,%2,%3},[%4];"
                 : "=r"(r[0]), "=r"(r[1]), "=r"(r[2]), "=r"(r[3]) : "r"(a));
}
__device__ __forceinline__ void ldsm2(uint32_t a, uint32_t r[2]) {
    asm volatile("ldmatrix.sync.aligned.m8n8.x2.shared.b16 {%0,%1},[%2];"
                 : "=r"(r[0]), "=r"(r[1]) : "r"(a));
}

__device__ __forceinline__ void mma_bf(float* c, const uint32_t* a, uint32_t b0, uint32_t b1) {
    asm volatile(
        "mma.sync.aligned.m16n8k16.row.col.f32.bf16.bf16.f32 "
        "{%0,%1,%2,%3},{%4,%5,%6,%7},{%8,%9},{%0,%1,%2,%3};"
        : "+f"(c[0]), "+f"(c[1]), "+f"(c[2]), "+f"(c[3])
        : "r"(a[0]), "r"(a[1]), "r"(a[2]), "r"(a[3]), "r"(b0), "r"(b1));
}

// C[NT n8] (+)= A[m16 x 16*KSTEPS] @ B[.][.]; single m-tile per warp.
// A row-major bf16, B stored [n][k] row-major bf16 (stride BKS halves).
template <int KSTEPS, int NT, int BKS>
__device__ __forceinline__ void gemm1m(uint32_t aA, uint32_t bA, uint32_t bAo,
                                       float c[NT][4]) {
#pragma unroll
    for (int ks = 0; ks < KSTEPS; ks++) {
        uint32_t a[4];
        ldsm4(aA, a);
#pragma unroll
        for (int p = 0; p < NT / 2; p++) {
            uint32_t b[4];
            ldsm4(bA + p * (16 * BKS * 2), b);
            mma_bf(c[2 * p],     a, b[0], b[1]);
            mma_bf(c[2 * p + 1], a, b[2], b[3]);
        }
        if constexpr (NT & 1) {
            uint32_t b[2];
            ldsm2(bAo, b);
            mma_bf(c[NT - 1], a, b[0], b[1]);
        }
        aA += 32; bA += 32; bAo += 32;
    }
}

// relu(c + bias) -> bf16x2 -> hb (word stride 60)
template <int NT>
__device__ __forceinline__ void store_h(const float c[NT][4], const float* __restrict__ bias,
                                        uint32_t* __restrict__ hb, int nb, int mrow, int g, int t) {
#pragma unroll
    for (int nt = 0; nt < NT; nt++) {
        int cc = nb + nt * 8 + 2 * t;
        float2 b = *(const float2*)&bias[cc];
#pragma unroll
        for (int h = 0; h < 2; h++) {
            int row = mrow + h * 8 + g;
            float v0 = fmaxf(c[nt][2 * h + 0] + b.x, 0.f);
            float v1 = fmaxf(c[nt][2 * h + 1] + b.y, 0.f);
            __nv_bfloat162 p = __floats2bfloat162_rn(v0, v1);
            hb[row * 60 + (cc >> 1)] = *(uint32_t*)&p;
        }
    }
}

// stage W1 slice [64 k][100 n] fp32 -> [112 n][72 k-stride] bf16 (pad pre-zeroed)
__device__ __forceinline__ void stageW1(const float* __restrict__ Wg,
                                        __nv_bfloat16* __restrict__ dst, int tid) {
#pragma unroll 1
    for (int idx = tid; idx < KD * NH; idx += NTH) {
        int kk = idx / NH, n = idx - kk * NH;
        dst[n * W1KS + kk] = __float2bfloat16(Wg[idx]);
    }
}

__global__ void __launch_bounds__(NTH, 1) flow_bf16(
    const float* __restrict__ e,
    const float* __restrict__ sW1, const float* __restrict__ sb1,
    const float* __restrict__ sW2, const float* __restrict__ sb2,
    const float* __restrict__ sW3, const float* __restrict__ sb3,
    const float* __restrict__ tW1, const float* __restrict__ tb1,
    const float* __restrict__ tW2, const float* __restrict__ tb2,
    const float* __restrict__ tW3, const float* __restrict__ tb3,
    float* __restrict__ zout, float* __restrict__ ldout)
{
    extern __shared__ float smf[];
    uint32_t* smu = (uint32_t*)smf;
    __nv_bfloat16* smh = (__nv_bfloat16*)smf;

    const int tid = threadIdx.x;
    const int lane = tid & 31, wid = tid >> 5;
    const int g = lane >> 2, t = lane & 3;
    const int mw = wid & 3, nw = wid >> 2;
    const int mrow = mw * 16;
    const int nb2 = nw * 56;   // GEMM1/2: 7 n-tiles per warp
    const int nb3 = nw * 32;   // GEMM3:   4 n-tiles per warp
    const long rowBase = (long)blockIdx.x * TB;

    // ---- preload: zero weight regions, fill transposed bf16 weights + biases ----
    for (int w = tid; w < O_H1S; w += NTH) smu[w] = 0u;
    __syncthreads();
    for (int idx = tid; idx < NH * NH; idx += NTH) {
        int in = idx / NH, out = idx - in * NH;
        smh[O_W2S * 2 + out * WKS + in] = __float2bfloat16(sW2[idx]);
        smh[O_W2T * 2 + out * WKS + in] = __float2bfloat16(tW2[idx]);
    }
    for (int idx = tid; idx < NH * KD; idx += NTH) {
        int in = idx / KD, out = idx - in * KD;
        smh[O_W3S * 2 + out * WKS + in] = __float2bfloat16(sW3[idx]);
        smh[O_W3T * 2 + out * WKS + in] = __float2bfloat16(tW3[idx]);
    }
    for (int idx = tid; idx < NPAD; idx += NTH) {
        smf[O_B1S + idx] = (idx < NH) ? sb1[idx] : 0.f;
        smf[O_B2S + idx] = (idx < NH) ? sb2[idx] : 0.f;
        smf[O_B1T + idx] = (idx < NH) ? tb1[idx] : 0.f;
        smf[O_B2T + idx] = (idx < NH) ? tb2[idx] : 0.f;
    }
    for (int idx = tid; idx < KD; idx += NTH) {
        smf[O_B3S + idx] = sb3[idx];
        smf[O_B3T + idx] = tb3[idx];
    }

    // ---- ldmatrix address precompute ----
    const uint32_t smb = sm_u32(smf);
    const int aRow = lane & 15, aK = (lane >> 4) << 3;
    const uint32_t aH1S = smb + O_H1S * 4 + ((mrow + aRow) * WKS + aK) * 2;
    const uint32_t aH1T = smb + O_H1T * 4 + ((mrow + aRow) * WKS + aK) * 2;
    const uint32_t aH2S = smb + O_H2S * 4 + ((mrow + aRow) * WKS + aK) * 2;
    const uint32_t aH2T = smb + O_H2T * 4 + ((mrow + aRow) * WKS + aK) * 2;
    const uint32_t aZB  = smb + O_ZB  * 4 + ((mrow + aRow) * ZBS + aK) * 2;
    const int bRow  = (lane & 7) + ((lane >> 4) << 3);
    const int bK    = ((lane >> 3) & 1) << 3;
    const int bORow = lane & 7;
    const uint32_t bW2S  = smb + O_W2S * 4 + ((nb2 + bRow) * WKS + bK) * 2;
    const uint32_t bW2So = smb + O_W2S * 4 + ((nb2 + 48 + bORow) * WKS + bK) * 2;
    const uint32_t bW2T  = smb + O_W2T * 4 + ((nb2 + bRow) * WKS + bK) * 2;
    const uint32_t bW2To = smb + O_W2T * 4 + ((nb2 + 48 + bORow) * WKS + bK) * 2;
    const uint32_t bW3S  = smb + O_W3S * 4 + ((nb3 + bRow) * WKS + bK) * 2;
    const uint32_t bW3T  = smb + O_W3T * 4 + ((nb3 + bRow) * WKS + bK) * 2;
    const uint32_t bW1S  = smb + O_W1S * 4 + ((nb2 + bRow) * W1KS + bK) * 2;
    const uint32_t bW1So = smb + O_W1S * 4 + ((nb2 + 48 + bORow) * W1KS + bK) * 2;
    const uint32_t bW1T  = smb + O_W1T * 4 + ((nb2 + bRow) * W1KS + bK) * 2;
    const uint32_t bW1To = smb + O_W1T * 4 + ((nb2 + 48 + bORow) * W1KS + bK) * 2;

    // persistent layer-1 accumulators (1 m-tile x 7 n-tiles each)
    float accS[7][4], accT[7][4];
#pragma unroll
    for (int b = 0; b < 7; b++)
#pragma unroll
        for (int q = 0; q < 4; q++) { accS[b][q] = 0.f; accT[b][q] = 0.f; }
    float ldacc[2] = {0.f, 0.f};

    __syncthreads();

    for (int i = 0; i < DIMS; i++) {
        // ---- Phase A: acc += z_{i-1} @ W1[i-1]; h1s/h1t stores ----
        if (i > 0) {
            gemm1m<4, 7, W1KS>(aZB, bW1S, bW1So, accS);
            gemm1m<4, 7, W1KS>(aZB, bW1T, bW1To, accT);
        }
        store_h<7>(accS, smf + O_B1S, smu + O_H1S, nb2, mrow, g, t);
        store_h<7>(accT, smf + O_B1T, smu + O_H1T, nb2, mrow, g, t);
        __syncthreads();

        // ---- Phase B: GEMM2-s + GEMM2-t; stage W1 slice i ----
        {
            float D[7][4] = {};
            gemm1m<7, 7, WKS>(aH1S, bW2S, bW2So, D);
            store_h<7>(D, smf + O_B2S, smu + O_H2S, nb2, mrow, g, t);
        }
        if (i < DIMS - 1) stageW1(sW1 + (size_t)i * KD * NH, smh + O_W1S * 2, tid);
        {
            float D[7][4] = {};
            gemm1m<7, 7, WKS>(aH1T, bW2T, bW2To, D);
            store_h<7>(D, smf + O_B2T, smu + O_H2T, nb2, mrow, g, t);
        }
        if (i < DIMS - 1) stageW1(tW1 + (size_t)i * KD * NH, smh + O_W1T * 2, tid);
        __syncthreads();

        // ---- Phase C: GEMM3-s -> sv (regs); GEMM3-t -> t; z epilogue ----
        {
            // prefetch e (latency hidden under the two GEMM3s)
            float2 eV[8];
#pragma unroll
            for (int nt = 0; nt < 4; nt++)
#pragma unroll
                for (int h = 0; h < 2; h++) {
                    int row = mrow + h * 8 + g;
                    eV[nt * 2 + h] = *(const float2*)&e[(rowBase + row) * TOT + i * KD + nb3 + nt * 8 + 2 * t];
                }

            float Ds[4][4] = {};
            gemm1m<7, 4, WKS>(aH2S, bW3S, 0, Ds);
            float sv[4][4];
#pragma unroll
            for (int nt = 0; nt < 4; nt++) {
                int cc = nb3 + nt * 8 + 2 * t;
                float2 b3 = *(const float2*)&smf[O_B3S + cc];
#pragma unroll
                for (int h = 0; h < 2; h++) {
                    float v0 = sigm(Ds[nt][2 * h + 0] + b3.x);
                    float v1 = sigm(Ds[nt][2 * h + 1] + b3.y);
                    sv[nt][2 * h + 0] = v0;
                    sv[nt][2 * h + 1] = v1;
                    ldacc[h] += v0 + v1;
                }
            }

            float Dt[4][4] = {};
            gemm1m<7, 4, WKS>(aH2T, bW3T, 0, Dt);
#pragma unroll
            for (int nt = 0; nt < 4; nt++) {
                int cc = nb3 + nt * 8 + 2 * t;
                float2 b3 = *(const float2*)&smf[O_B3T + cc];
#pragma unroll
                for (int h = 0; h < 2; h++) {
                    int row = mrow + h * 8 + g;
                    float t0 = sigm(Dt[nt][2 * h + 0] + b3.x);
                    float t1 = sigm(Dt[nt][2 * h + 1] + b3.y);
                    float2 e2 = eV[nt * 2 + h];
                    float z0 = __expf(sv[nt][2 * h + 0]) * e2.x + t0;
                    float z1 = __expf(sv[nt][2 * h + 1]) * e2.y + t1;
                    *(float2*)&zout[(rowBase + row) * TOT + i * KD + cc] = make_float2(z0, z1);
                    __nv_bfloat162 zb = __floats2bfloat162_rn(z0, z1);
                    smu[O_ZB + row * 36 + (cc >> 1)] = *(uint32_t*)&zb;
                }
            }
        }
        __syncthreads();
    }

    // ---- logdet reduction: 8 partials per row ----
#pragma unroll
    for (int h = 0; h < 2; h++) {
        int row = mrow + h * 8 + g;
        smf[O_LDP + row * 8 + nw * 4 + t] = ldacc[h];
    }
    __syncthreads();
    if (tid < TB) {
        float v = 0.f;
#pragma unroll
        for (int q = 0; q < 8; q++) v += smf[O_LDP + tid * 8 + q];
        ldout[rowBase + tid] = v;
    }
}

extern "C" void kernel_launch(void* const* d_in, const int* in_sizes, int n_in,
                              void* d_out, int out_size) {
    const float* e   = (const float*)d_in[0];
    // d_in[1] = C (strictly upper-triangular DAG -> incremental layer-1 acc is exact)
    const float* sW1 = (const float*)d_in[2];
    const float* sb1 = (const float*)d_in[3];
    const float* sW2 = (const float*)d_in[4];
    const float* sb2 = (const float*)d_in[5];
    const float* sW3 = (const float*)d_in[6];
    const float* sb3 = (const float*)d_in[7];
    const float* tW1 = (const float*)d_in[8];
    const float* tb1 = (const float*)d_in[9];
    const float* tW2 = (const float*)d_in[10];
    const float* tb2 = (const float*)d_in[11];
    const float* tW3 = (const float*)d_in[12];
    const float* tb3 = (const float*)d_in[13];

    float* out = (float*)d_out;
    const int B = in_sizes[0] / TOT;
    float* zout  = out;
    float* ldout = out + (size_t)B * TOT;

    cudaFuncSetAttribute(flow_bf16, cudaFuncAttributeMaxDynamicSharedMemorySize,
                         SMW * (int)sizeof(float));

    flow_bf16<<<B / TB, NTH, SMW * sizeof(float)>>>(
        e, sW1, sb1, sW2, sb2, sW3, sb3,
        tW1, tb1, tW2, tb2, tW3, tb3,
        zout, ldout);
}

// round 6
// speedup vs baseline: 1.5997x; 1.5997x over previous
#include <cuda_runtime.h>
#include <cuda_bf16.h>
#include <cstdint>

#define NTH 512
constexpr int TB   = 128;
constexpr int NH   = 100;
constexpr int NPAD = 112;
constexpr int KD   = 64;
constexpr int DIMS = 8;
constexpr int TOT  = 512;
constexpr int WKS  = 120;   // halves: stride for W2/W3/H buffers (conflict-free ldmatrix)
constexpr int W1KS = 72;    // halves: W1 slice stride
constexpr int ZBS  = 72;    // halves: z-buffer stride (36 words)

// shared layout (word offsets)
constexpr int O_W2S = 0;                    // [112][60w]
constexpr int O_W2T = O_W2S + NPAD * 60;    // 6720
constexpr int O_W3S = O_W2T + NPAD * 60;    // 13440 [64][60w]
constexpr int O_W3T = O_W3S + 64 * 60;      // 17280
constexpr int O_W1S = O_W3T + 64 * 60;      // 21120 [112][36w]
constexpr int O_W1T = O_W1S + NPAD * 36;    // 25152
constexpr int O_HB1 = O_W1T + NPAD * 36;    // 29184 [128][60w]
constexpr int O_HB2 = O_HB1 + TB * 60;      // 36864 [128][60w]
constexpr int O_ZB  = O_HB2 + TB * 60;      // 44544 [128][36w] bf16 z
constexpr int O_LDP = O_ZB + TB * 36;       // 49152 [128][8]
constexpr int O_B1S = O_LDP + TB * 8;       // 50176
constexpr int O_B2S = O_B1S + NPAD;
constexpr int O_B3S = O_B2S + NPAD;
constexpr int O_B1T = O_B3S + KD;
constexpr int O_B2T = O_B1T + NPAD;
constexpr int O_B3T = O_B2T + NPAD;
constexpr int SMW   = O_B3T + KD;           // 50752 words = 203008 B

__device__ __forceinline__ float sigm(float x) {
    return __fdividef(1.0f, 1.0f + __expf(-x));
}

__device__ __forceinline__ uint32_t sm_u32(const void* p) {
    uint32_t a;
    asm("{ .reg .u64 t; cvta.to.shared.u64 t, %1; cvt.u32.u64 %0, t; }" : "=r"(a) : "l"(p));
    return a;
}

__device__ __forceinline__ void ldsm4(uint32_t a, uint32_t r[4]) {
    asm volatile("ldmatrix.sync.aligned.m8n8.x4.shared.b16 {%0,%1,%2,%3},[%4];"
                 : "=r"(r[0]), "=r"(r[1]), "=r"(r[2]), "=r"(r[3]) : "r"(a));
}
__device__ __forceinline__ void ldsm2(uint32_t a, uint32_t r[2]) {
    asm volatile("ldmatrix.sync.aligned.m8n8.x2.shared.b16 {%0,%1},[%2];"
                 : "=r"(r[0]), "=r"(r[1]) : "r"(a));
}

__device__ __forceinline__ void mma_bf(float* c, const uint32_t* a, uint32_t b0, uint32_t b1) {
    asm volatile(
        "mma.sync.aligned.m16n8k16.row.col.f32.bf16.bf16.f32 "
        "{%0,%1,%2,%3},{%4,%5,%6,%7},{%8,%9},{%0,%1,%2,%3};"
        : "+f"(c[0]), "+f"(c[1]), "+f"(c[2]), "+f"(c[3])
        : "r"(a[0]), "r"(a[1]), "r"(a[2]), "r"(a[3]), "r"(b0), "r"(b1));
}

// C[NT n8] (+)= A[m16 x 16*KSTEPS] @ B; one m-tile per warp.
// A row-major bf16, B stored [n][k] row-major bf16 (stride BKS halves).
template <int KSTEPS, int NT, int BKS>
__device__ __forceinline__ void gemm1m(uint32_t aA, uint32_t bA, uint32_t bAo,
                                       float c[NT][4]) {
#pragma unroll
    for (int ks = 0; ks < KSTEPS; ks++) {
        uint32_t a[4];
        ldsm4(aA, a);
#pragma unroll
        for (int p = 0; p < NT / 2; p++) {
            uint32_t b[4];
            ldsm4(bA + p * (16 * BKS * 2), b);
            mma_bf(c[2 * p],     a, b[0], b[1]);
            mma_bf(c[2 * p + 1], a, b[2], b[3]);
        }
        if constexpr (NT & 1) {
            uint32_t b[2];
            ldsm2(bAo, b);
            mma_bf(c[NT - 1], a, b[0], b[1]);
        }
        aA += 32; bA += 32; bAo += 32;
    }
}

// relu(c + bias) -> bf16x2 -> hb (word stride 60)
template <int NT>
__device__ __forceinline__ void store_h(const float c[NT][4], const float* __restrict__ bias,
                                        uint32_t* __restrict__ hb, int nb, int mrow, int g, int t) {
#pragma unroll
    for (int nt = 0; nt < NT; nt++) {
        int cc = nb + nt * 8 + 2 * t;
        float2 b = *(const float2*)&bias[cc];
#pragma unroll
        for (int h = 0; h < 2; h++) {
            int row = mrow + h * 8 + g;
            float v0 = fmaxf(c[nt][2 * h + 0] + b.x, 0.f);
            float v1 = fmaxf(c[nt][2 * h + 1] + b.y, 0.f);
            __nv_bfloat162 p = __floats2bfloat162_rn(v0, v1);
            hb[row * 60 + (cc >> 1)] = *(uint32_t*)&p;
        }
    }
}

// stage W1 slice [64 k][100 n] fp32 -> [112 n][72 k-stride] bf16 (pad pre-zeroed)
__device__ __forceinline__ void stageW1(const float* __restrict__ Wg,
                                        __nv_bfloat16* __restrict__ dst, int tid) {
#pragma unroll 1
    for (int idx = tid; idx < KD * NH; idx += NTH) {
        int kk = idx / NH, n = idx - kk * NH;
        dst[n * W1KS + kk] = __float2bfloat16(Wg[idx]);
    }
}

__global__ void __launch_bounds__(NTH, 1) flow_bf16(
    const float* __restrict__ e,
    const float* __restrict__ sW1, const float* __restrict__ sb1,
    const float* __restrict__ sW2, const float* __restrict__ sb2,
    const float* __restrict__ sW3, const float* __restrict__ sb3,
    const float* __restrict__ tW1, const float* __restrict__ tb1,
    const float* __restrict__ tW2, const float* __restrict__ tb2,
    const float* __restrict__ tW3, const float* __restrict__ tb3,
    float* __restrict__ zout, float* __restrict__ ldout)
{
    extern __shared__ float smf[];
    uint32_t* smu = (uint32_t*)smf;
    __nv_bfloat16* smh = (__nv_bfloat16*)smf;

    const int tid = threadIdx.x;
    const int lane = tid & 31, wid = tid >> 5;
    const int g = lane >> 2, t = lane & 3;
    const int mw = wid & 7, nw = wid >> 3;   // 8 m-warps x 2 n-groups
    const int mrow = mw * 16;
    const int nb2 = nw * 56;   // GEMM1/2: 7 n-tiles per group
    const int nb3 = nw * 32;   // GEMM3:   4 n-tiles per group
    const long rowBase = (long)blockIdx.x * TB;

    // ---- preload: zero weight regions, fill transposed bf16 weights + biases ----
    for (int w = tid; w < O_HB1; w += NTH) smu[w] = 0u;
    __syncthreads();
    for (int idx = tid; idx < NH * NH; idx += NTH) {
        int in = idx / NH, out = idx - in * NH;
        smh[O_W2S * 2 + out * WKS + in] = __float2bfloat16(sW2[idx]);
        smh[O_W2T * 2 + out * WKS + in] = __float2bfloat16(tW2[idx]);
    }
    for (int idx = tid; idx < NH * KD; idx += NTH) {
        int in = idx / KD, out = idx - in * KD;
        smh[O_W3S * 2 + out * WKS + in] = __float2bfloat16(sW3[idx]);
        smh[O_W3T * 2 + out * WKS + in] = __float2bfloat16(tW3[idx]);
    }
    for (int idx = tid; idx < NPAD; idx += NTH) {
        smf[O_B1S + idx] = (idx < NH) ? sb1[idx] : 0.f;
        smf[O_B2S + idx] = (idx < NH) ? sb2[idx] : 0.f;
        smf[O_B1T + idx] = (idx < NH) ? tb1[idx] : 0.f;
        smf[O_B2T + idx] = (idx < NH) ? tb2[idx] : 0.f;
    }
    for (int idx = tid; idx < KD; idx += NTH) {
        smf[O_B3S + idx] = sb3[idx];
        smf[O_B3T + idx] = tb3[idx];
    }

    // ---- ldmatrix address precompute ----
    const uint32_t smb = sm_u32(smf);
    const int aRow = lane & 15, aK = (lane >> 4) << 3;
    const uint32_t aHB1 = smb + O_HB1 * 4 + ((mrow + aRow) * WKS + aK) * 2;
    const uint32_t aHB2 = smb + O_HB2 * 4 + ((mrow + aRow) * WKS + aK) * 2;
    const uint32_t aZB  = smb + O_ZB  * 4 + ((mrow + aRow) * ZBS + aK) * 2;
    const int bRow  = (lane & 7) + ((lane >> 4) << 3);
    const int bK    = ((lane >> 3) & 1) << 3;
    const int bORow = lane & 7;
    const uint32_t bW2S  = smb + O_W2S * 4 + ((nb2 + bRow) * WKS + bK) * 2;
    const uint32_t bW2So = smb + O_W2S * 4 + ((nb2 + 48 + bORow) * WKS + bK) * 2;
    const uint32_t bW2T  = smb + O_W2T * 4 + ((nb2 + bRow) * WKS + bK) * 2;
    const uint32_t bW2To = smb + O_W2T * 4 + ((nb2 + 48 + bORow) * WKS + bK) * 2;
    const uint32_t bW3S  = smb + O_W3S * 4 + ((nb3 + bRow) * WKS + bK) * 2;
    const uint32_t bW3T  = smb + O_W3T * 4 + ((nb3 + bRow) * WKS + bK) * 2;
    const uint32_t bW1S  = smb + O_W1S * 4 + ((nb2 + bRow) * W1KS + bK) * 2;
    const uint32_t bW1So = smb + O_W1S * 4 + ((nb2 + 48 + bORow) * W1KS + bK) * 2;
    const uint32_t bW1T  = smb + O_W1T * 4 + ((nb2 + bRow) * W1KS + bK) * 2;
    const uint32_t bW1To = smb + O_W1T * 4 + ((nb2 + 48 + bORow) * W1KS + bK) * 2;

    // persistent layer-1 accumulators: 1 m-tile x 7 n-tiles each
    float accS[7][4], accT[7][4];
#pragma unroll
    for (int b = 0; b < 7; b++)
#pragma unroll
        for (int q = 0; q < 4; q++) { accS[b][q] = 0.f; accT[b][q] = 0.f; }
    float ldacc[2] = {0.f, 0.f};

    __syncthreads();

    for (int i = 0; i < DIMS; i++) {
        // ---- A: acc += z_{i-1} @ W1[i-1]; h1s -> HB1 ----
        if (i > 0) {
            gemm1m<4, 7, W1KS>(aZB, bW1S, bW1So, accS);
            gemm1m<4, 7, W1KS>(aZB, bW1T, bW1To, accT);
        }
        store_h<7>(accS, smf + O_B1S, smu + O_HB1, nb2, mrow, g, t);
        __syncthreads();

        // ---- B: GEMM2-s ----
        {
            float D[7][4] = {};
            gemm1m<7, 7, WKS>(aHB1, bW2S, bW2So, D);
            store_h<7>(D, smf + O_B2S, smu + O_HB2, nb2, mrow, g, t);
        }
        __syncthreads();

        // ---- C: GEMM3-s -> sv (regs) + logdet; h1t -> HB1; stage W1s slice i ----
        float sv[4][4];
        {
            float Ds[4][4] = {};
            gemm1m<7, 4, WKS>(aHB2, bW3S, 0, Ds);
#pragma unroll
            for (int nt = 0; nt < 4; nt++) {
                int cc = nb3 + nt * 8 + 2 * t;
                float2 b3 = *(const float2*)&smf[O_B3S + cc];
#pragma unroll
                for (int h = 0; h < 2; h++) {
                    float v0 = sigm(Ds[nt][2 * h + 0] + b3.x);
                    float v1 = sigm(Ds[nt][2 * h + 1] + b3.y);
                    sv[nt][2 * h + 0] = v0;
                    sv[nt][2 * h + 1] = v1;
                    ldacc[h] += v0 + v1;
                }
            }
            store_h<7>(accT, smf + O_B1T, smu + O_HB1, nb2, mrow, g, t);
            if (i < DIMS - 1) stageW1(sW1 + (size_t)i * KD * NH, smh + O_W1S * 2, tid);
        }
        __syncthreads();

        // ---- D: GEMM2-t; stage W1t slice i ----
        {
            float D[7][4] = {};
            gemm1m<7, 7, WKS>(aHB1, bW2T, bW2To, D);
            store_h<7>(D, smf + O_B2T, smu + O_HB2, nb2, mrow, g, t);
            if (i < DIMS - 1) stageW1(tW1 + (size_t)i * KD * NH, smh + O_W1T * 2, tid);
        }
        __syncthreads();

        // ---- E: GEMM3-t -> t; z = exp(sv)*e + t; STG + z(bf16) -> ZB ----
        {
            float Dt[4][4] = {};
            gemm1m<7, 4, WKS>(aHB2, bW3T, 0, Dt);
#pragma unroll
            for (int nt = 0; nt < 4; nt++) {
                int cc = nb3 + nt * 8 + 2 * t;
                float2 b3 = *(const float2*)&smf[O_B3T + cc];
#pragma unroll
                for (int h = 0; h < 2; h++) {
                    int row = mrow + h * 8 + g;
                    long gidx = (rowBase + row) * TOT + i * KD + cc;
                    float t0 = sigm(Dt[nt][2 * h + 0] + b3.x);
                    float t1 = sigm(Dt[nt][2 * h + 1] + b3.y);
                    float2 e2 = *(const float2*)&e[gidx];
                    float z0 = __expf(sv[nt][2 * h + 0]) * e2.x + t0;
                    float z1 = __expf(sv[nt][2 * h + 1]) * e2.y + t1;
                    *(float2*)&zout[gidx] = make_float2(z0, z1);
                    __nv_bfloat162 zb = __floats2bfloat162_rn(z0, z1);
                    smu[O_ZB + row * 36 + (cc >> 1)] = *(uint32_t*)&zb;
                }
            }
        }
        __syncthreads();
    }

    // ---- logdet reduction: 8 partials per row ----
#pragma unroll
    for (int h = 0; h < 2; h++) {
        int row = mrow + h * 8 + g;
        smf[O_LDP + row * 8 + nw * 4 + t] = ldacc[h];
    }
    __syncthreads();
    if (tid < TB) {
        float v = 0.f;
#pragma unroll
        for (int q = 0; q < 8; q++) v += smf[O_LDP + tid * 8 + q];
        ldout[rowBase + tid] = v;
    }
}

extern "C" void kernel_launch(void* const* d_in, const int* in_sizes, int n_in,
                              void* d_out, int out_size) {
    const float* e   = (const float*)d_in[0];
    // d_in[1] = C (strictly upper-triangular DAG -> incremental layer-1 acc is exact)
    const float* sW1 = (const float*)d_in[2];
    const float* sb1 = (const float*)d_in[3];
    const float* sW2 = (const float*)d_in[4];
    const float* sb2 = (const float*)d_in[5];
    const float* sW3 = (const float*)d_in[6];
    const float* sb3 = (const float*)d_in[7];
    const float* tW1 = (const float*)d_in[8];
    const float* tb1 = (const float*)d_in[9];
    const float* tW2 = (const float*)d_in[10];
    const float* tb2 = (const float*)d_in[11];
    const float* tW3 = (const float*)d_in[12];
    const float* tb3 = (const float*)d_in[13];

    float* out = (float*)d_out;
    const int B = in_sizes[0] / TOT;
    float* zout  = out;
    float* ldout = out + (size_t)B * TOT;

    cudaFuncSetAttribute(flow_bf16, cudaFuncAttributeMaxDynamicSharedMemorySize,
                         SMW * (int)sizeof(float));

    flow_bf16<<<B / TB, NTH, SMW * sizeof(float)>>>(
        e, sW1, sb1, sW2, sb2, sW3, sb3,
        tW1, tb1, tW2, tb2, tW3, tb3,
        zout, ldout);
}